// round 7
// baseline (speedup 1.0000x reference)
#include <cuda_runtime.h>
#include <cuda_bf16.h>
#include <cstdint>
#include <math.h>

// Row-normalize two [32,1024,1024] fp32 tensors, single pass, out = concat.
//
// R5 design: decoupled read stream. cp.async.bulk (non-tensor TMA) fills a
// 6-stage x 32KB SMEM ring; the producer never blocks on compute, so the
// DRAM read stream stays saturated independent of the reduce/store bubble.
// 8 consumer warps each take one 4KB row per tile: LDS.128 x8, butterfly
// reduce, scale, STG.128 (streaming) straight to gmem.
// R2 baseline: 76.0us, DRAM 77.4% (register-file-limited in-flight).
// Predicted: ~68-70us, DRAM ~86%.

static constexpr int ROWS_TOTAL      = 65536;
static constexpr int ROWS_PER_TENSOR = 32768;
static constexpr int TILE_ROWS       = 8;                    // 1 row / warp
static constexpr int ROW_BYTES       = 4096;
static constexpr int TILE_BYTES      = TILE_ROWS * ROW_BYTES; // 32 KB
static constexpr int STAGES          = 6;
static constexpr int THREADS         = 256;
static constexpr int ROWS_PER_CTA    = 64;
static constexpr int TILES_PER_CTA   = ROWS_PER_CTA / TILE_ROWS; // 8
static constexpr int GRID            = ROWS_TOTAL / ROWS_PER_CTA; // 1024

static constexpr int SMEM_TILES_OFF  = 1024;  // barriers live in [0, 1024)
static constexpr int SMEM_BYTES      = SMEM_TILES_OFF + STAGES * TILE_BYTES; // 197632

__device__ __forceinline__ void mbar_init(uint32_t addr, uint32_t count) {
    asm volatile("mbarrier.init.shared.b64 [%0], %1;" :: "r"(addr), "r"(count) : "memory");
}
__device__ __forceinline__ void mbar_expect_tx(uint32_t addr, uint32_t bytes) {
    asm volatile("mbarrier.arrive.expect_tx.shared.b64 _, [%0], %1;"
                 :: "r"(addr), "r"(bytes) : "memory");
}
__device__ __forceinline__ void bulk_ld(uint32_t dst_smem, const void* src, uint32_t bytes,
                                        uint32_t mbar) {
    asm volatile(
        "cp.async.bulk.shared::cluster.global.mbarrier::complete_tx::bytes "
        "[%0], [%1], %2, [%3];"
        :: "r"(dst_smem), "l"(src), "r"(bytes), "r"(mbar) : "memory");
}
__device__ __forceinline__ void mbar_wait(uint32_t addr, uint32_t parity) {
    uint32_t done;
    asm volatile(
        "{\n\t.reg .pred p;\n\t"
        "mbarrier.try_wait.parity.acquire.cta.shared::cta.b64 p, [%1], %2;\n\t"
        "selp.b32 %0, 1, 0, p;\n\t}"
        : "=r"(done) : "r"(addr), "r"(parity) : "memory");
    if (!done) {
        asm volatile(
            "{\n\t.reg .pred P1;\n\t"
            "WAIT_LOOP_%=:\n\t"
            "mbarrier.try_wait.parity.acquire.cta.shared::cta.b64 P1, [%0], %1, 0x989680;\n\t"
            "@P1 bra.uni WAIT_DONE_%=;\n\t"
            "bra.uni WAIT_LOOP_%=;\n\t"
            "WAIT_DONE_%=:\n\t}"
            :: "r"(addr), "r"(parity) : "memory");
    }
}

__global__ __launch_bounds__(THREADS, 1)
void normalizer_tma_kernel(const float* __restrict__ adj0,
                           const float* __restrict__ adj1,
                           float* __restrict__ out)
{
    extern __shared__ __align__(128) char smem[];
    const uint32_t smem_base = (uint32_t)__cvta_generic_to_shared(smem);
    const int tid  = threadIdx.x;
    const int wid  = tid >> 5;
    const int lane = tid & 31;

    // This CTA owns 64 consecutive rows; boundary at 32768 is 64-aligned,
    // so all rows come from one source tensor.
    const long long row0 = (long long)blockIdx.x * ROWS_PER_CTA;
    const bool second = (row0 >= ROWS_PER_TENSOR);
    const float* src_base = (second ? adj1 : adj0)
                          + (second ? (row0 - ROWS_PER_TENSOR) : row0) * 1024;
    float* out_base = out + row0 * 1024;

    // Init one full-barrier per stage (producer expect_tx is the only arrive).
    if (tid == 0) {
        for (int s = 0; s < STAGES; s++)
            mbar_init(smem_base + s * 8, 1);
    }
    __syncthreads();

    // Prologue: fill all stages (TILES_PER_CTA >= STAGES).
    if (tid == 0) {
#pragma unroll
        for (int k = 0; k < STAGES; k++) {
            const uint32_t mbar = smem_base + k * 8;
            mbar_expect_tx(mbar, TILE_BYTES);
            bulk_ld(smem_base + SMEM_TILES_OFF + k * TILE_BYTES,
                    src_base + (long long)k * (TILE_ROWS * 1024),
                    TILE_BYTES, mbar);
        }
    }

    for (int i = 0; i < TILES_PER_CTA; i++) {
        const int s     = i % STAGES;
        const int phase = (i / STAGES) & 1;
        const uint32_t mbar = smem_base + s * 8;

        mbar_wait(mbar, phase);

        // Warp w consumes row w of the tile: 8 conflict-free LDS.128 per lane.
        const float4* r4 = reinterpret_cast<const float4*>(
            smem + SMEM_TILES_OFF + s * TILE_BYTES + wid * ROW_BYTES) + lane;
        float4 v[8];
        float sum = 0.0f;
#pragma unroll
        for (int j = 0; j < 8; j++) {
            v[j] = r4[j * 32];
            sum += (v[j].x + v[j].y) + (v[j].z + v[j].w);
        }
#pragma unroll
        for (int off = 16; off > 0; off >>= 1)
            sum += __shfl_xor_sync(0xffffffffu, sum, off);

        float inv = 1.0f / sum;
        if (!isfinite(inv)) inv = 0.0f;

        float4* o = reinterpret_cast<float4*>(
            out_base + (long long)(i * TILE_ROWS + wid) * 1024) + lane;
#pragma unroll
        for (int j = 0; j < 8; j++) {
            float4 t = v[j];
            t.x *= inv; t.y *= inv; t.z *= inv; t.w *= inv;
            __stcs(o + j * 32, t);
        }

        // All warps done reading stage s -> safe to refill it.
        __syncthreads();
        const int n = i + STAGES;
        if (tid == 0 && n < TILES_PER_CTA) {
            mbar_expect_tx(mbar, TILE_BYTES);
            bulk_ld(smem_base + SMEM_TILES_OFF + s * TILE_BYTES,
                    src_base + (long long)n * (TILE_ROWS * 1024),
                    TILE_BYTES, mbar);
        }
    }
}

extern "C" void kernel_launch(void* const* d_in, const int* in_sizes, int n_in,
                              void* d_out, int out_size)
{
    const float* adj0 = (const float*)d_in[0];
    const float* adj1 = (const float*)d_in[1];
    float* out = (float*)d_out;

    cudaFuncSetAttribute(normalizer_tma_kernel,
                         cudaFuncAttributeMaxDynamicSharedMemorySize, SMEM_BYTES);
    normalizer_tma_kernel<<<GRID, THREADS, SMEM_BYTES>>>(adj0, adj1, out);
}

// round 8
// speedup vs baseline: 1.0233x; 1.0233x over previous
#include <cuda_runtime.h>
#include <cuda_bf16.h>
#include <math.h>

// Row-normalize two [32,1024,1024] fp32 tensors, single pass over DRAM.
// out[row,:] = in[row,:] * inv(sum(in[row,:])), inv zeroed if non-finite.
//
// R7 design: warp-per-row, TWO phases over the row, buffering in cache not
// registers.
//   Phase 1: 8x LDG.128 (default caching -> lines land in L1/L2), lane sum,
//            butterfly reduce.
//   Phase 2: re-load the same 8 float4 (L1/L2 hits, ~40-240cyc, not DRAM),
//            scale, STG.128 streaming.
// This drops regs 80 -> ~40 so occupancy recovers to ~48 warps/SM while the
// per-row issue bubble stays small -> higher LDG duty cycle than R2.
// History: R1 97.7us/71.7%; R2 76.0us/77.4% (best); R5 pipeline 81.3us/72.2%.
// Predicted: ~69us kernel, DRAM ~84%.

static constexpr int ROWS_PER_TENSOR = 32 * 1024;            // 32768
static constexpr int TOTAL_ROWS      = 2 * ROWS_PER_TENSOR;  // 65536
static constexpr int WARPS_PER_BLOCK = 8;
static constexpr int THREADS         = WARPS_PER_BLOCK * 32;
static constexpr int BLOCKS          = TOTAL_ROWS / WARPS_PER_BLOCK; // 8192

__global__ __launch_bounds__(THREADS, 6)
void normalizer_kernel(const float* __restrict__ adj0,
                       const float* __restrict__ adj1,
                       float* __restrict__ out)
{
    const int gwarp = (blockIdx.x * WARPS_PER_BLOCK) + (threadIdx.x >> 5);
    const int lane  = threadIdx.x & 31;

    const bool second = (gwarp >= ROWS_PER_TENSOR);
    const float* src  = second ? adj1 : adj0;
    const long long local_row = second ? (long long)(gwarp - ROWS_PER_TENSOR)
                                       : (long long)gwarp;

    const float4* in = reinterpret_cast<const float4*>(src + local_row * 1024) + lane;
    float4*       o  = reinterpret_cast<float4*>(out + (long long)gwarp * 1024) + lane;

    // Phase 1: sum the row. Default-cached loads so the lines stay hot in
    // L1/L2 for the phase-2 re-read. 8 independent LDG.128 -> MLP=8.
    float s = 0.0f;
#pragma unroll
    for (int i = 0; i < 8; i++) {
        const float4 v = __ldg(in + i * 32);
        s += (v.x + v.y) + (v.z + v.w);
    }

#pragma unroll
    for (int off = 16; off > 0; off >>= 1)
        s += __shfl_xor_sync(0xffffffffu, s, off);

    float inv = 1.0f / s;
    if (!isfinite(inv)) inv = 0.0f;

    // Phase 2: re-read from cache, scale, stream the stores out.
#pragma unroll
    for (int i = 0; i < 8; i++) {
        float4 t = __ldg(in + i * 32);
        t.x *= inv; t.y *= inv; t.z *= inv; t.w *= inv;
        __stcs(o + i * 32, t);
    }
}

extern "C" void kernel_launch(void* const* d_in, const int* in_sizes, int n_in,
                              void* d_out, int out_size)
{
    const float* adj0 = (const float*)d_in[0];
    const float* adj1 = (const float*)d_in[1];
    float* out = (float*)d_out;

    normalizer_kernel<<<BLOCKS, THREADS>>>(adj0, adj1, out);
}